// round 11
// baseline (speedup 1.0000x reference)
#include <cuda_runtime.h>
#include <math.h>

#define NBATCH 8
#define CHN    256
#define CQ     64
#define NCLUS  128
#define WIN    144
#define HH     96
#define WWID   96
#define LTOT   (HH*WWID)      /* 9216 */
#define NWIN   (LTOT/WIN)     /* 64 */
#define W3     (3*WIN)        /* 432 */
#define NCHUNK (LTOT/128)     /* 72 */

/* ---------------- device scratch ---------------- */
__device__ float g_xe[NBATCH*LTOT*CQ];          // x_embed (n,l,c)
__device__ float g_ye[NBATCH*LTOT*CHN];         // y_embed (n,l,ch)
__device__ float g_wt[CHN*CHN];                 // w_asm transposed [ci][co]
__device__ float g_mt[CQ*NCLUS];                // means transposed [k][c]
__device__ int   g_bucket[NBATCH*LTOT];
__device__ int   g_lrank[NBATCH*LTOT];
__device__ int   g_chist[NBATCH*NCHUNK*NCLUS];
__device__ int   g_cbase[NBATCH*NCHUNK*NCLUS];
__device__ int   g_indices[NBATCH*LTOT];        // sorted pos -> original l
__device__ float g_qs[NBATCH*LTOT*CQ];          // gathered raw x rows (sorted order)
__device__ float g_kn[NBATCH*LTOT*CQ];          // gathered normalized x rows
__device__ float g_vs[NBATCH*LTOT*CHN];         // gathered y rows
__device__ float g_raw[(size_t)NBATCH*NWIN*WIN*W3];  // raw scores / P in place
__device__ float g_ret[NBATCH*LTOT*CHN];        // attention output at ORIGINAL l

/* ---------------- K0: transposes ---------------- */
__global__ void k_prep(const float* __restrict__ wasm, const float* __restrict__ means)
{
    int idx = blockIdx.x * 256 + threadIdx.x;
    if (idx < CHN*CHN) {
        int ci = idx >> 8, co = idx & 255;
        g_wt[idx] = wasm[co*CHN + ci];
    } else {
        int j = idx - CHN*CHN;
        if (j < CQ*NCLUS) {
            int k = j >> 7, c = j & 127;
            g_mt[j] = means[c*CQ + k];   // NR=1 -> means[0][c][k]
        }
    }
}

/* ---------------- K1: conv3x3 -> g_xe ---------------- */
__global__ void k_conv3(const float* __restrict__ x, const float* __restrict__ w,
                        const float* __restrict__ bias)
{
    __shared__ float xin[16*3*34];     // [ci][dy][col]
    __shared__ float ws[16*9*64];      // [ci*9+tap][cout]
    const int wt = blockIdx.x;         // 0..2 (w tile of 32)
    const int h  = blockIdx.y;         // 0..95
    const int n  = blockIdx.z;
    const int t  = threadIdx.x;        // 256
    const int cout = t & 63;
    const int grp  = t >> 6;           // 0..3, 8 pixels each
    const int w0 = wt * 32;

    float acc[8];
    const float bv = bias[cout];
#pragma unroll
    for (int p = 0; p < 8; p++) acc[p] = bv;

    for (int cc = 0; cc < CHN; cc += 16) {
        __syncthreads();
        // weights: 64 cout x 16 ci x 9 taps = 9216 floats
        for (int idx = t; idx < 64*144; idx += 256) {
            int co = idx / 144;
            int r  = idx - co * 144;         // ci*9 + tap
            ws[r*64 + co] = w[co*2304 + cc*9 + r];
        }
        // input: 16 ci x 3 rows x 34 cols
        for (int idx = t; idx < 16*3*34; idx += 256) {
            int ci = idx / 102;
            int r  = idx - ci*102;
            int dy = r / 34;
            int c  = r - dy*34;
            int hi = h + dy - 1;
            int wi = w0 - 1 + c;
            float v = 0.f;
            if (hi >= 0 && hi < HH && wi >= 0 && wi < WWID)
                v = x[((size_t)(n*CHN + cc + ci)*HH + hi)*WWID + wi];
            xin[idx] = v;
        }
        __syncthreads();

        for (int ci = 0; ci < 16; ci++) {
#pragma unroll
            for (int dy = 0; dy < 3; dy++) {
                float xv[10];
                const float* xr = &xin[(ci*3 + dy)*34 + grp*8];
#pragma unroll
                for (int q = 0; q < 10; q++) xv[q] = xr[q];
#pragma unroll
                for (int kx = 0; kx < 3; kx++) {
                    float wv = ws[(ci*9 + dy*3 + kx)*64 + cout];
#pragma unroll
                    for (int p = 0; p < 8; p++) acc[p] += wv * xv[p + kx];
                }
            }
        }
    }
    // store: g_xe[n][l][cout]
#pragma unroll
    for (int p = 0; p < 8; p++) {
        int l = h*WWID + w0 + grp*8 + p;
        g_xe[((size_t)n*LTOT + l)*CQ + cout] = acc[p];
    }
}

/* ---------------- K2: conv1x1 (GEMM) -> g_ye ---------------- */
__global__ void k_conv1(const float* __restrict__ x, const float* __restrict__ bias)
{
    __shared__ float As[16*64];
    __shared__ float Bs[16*64];
    const int lt = blockIdx.x;   // 0..143
    const int ct = blockIdx.y;   // 0..3
    const int n  = blockIdx.z;
    const int t  = threadIdx.x;
    const int tx = t & 15, ty = t >> 4;
    const int l0 = lt*64, c0 = ct*64;
    const float* xn = x + (size_t)n*CHN*LTOT;

    float acc[4][4];
#pragma unroll
    for (int r = 0; r < 4; r++)
#pragma unroll
        for (int c = 0; c < 4; c++) acc[r][c] = 0.f;

    for (int k0 = 0; k0 < CHN; k0 += 16) {
        int idx = t;
#pragma unroll
        for (int r = 0; r < 4; r++) {
            int ci = idx >> 6, ll = idx & 63;
            As[ci*64 + ll] = xn[(size_t)(k0 + ci)*LTOT + l0 + ll];
            idx += 256;
        }
        idx = t;
#pragma unroll
        for (int r = 0; r < 4; r++) {
            int ci = idx >> 6, co = idx & 63;
            Bs[ci*64 + co] = g_wt[(k0 + ci)*CHN + c0 + co];
            idx += 256;
        }
        __syncthreads();
#pragma unroll
        for (int k = 0; k < 16; k++) {
            float a0 = As[k*64 + ty];
            float a1 = As[k*64 + ty + 16];
            float a2 = As[k*64 + ty + 32];
            float a3 = As[k*64 + ty + 48];
            float4 b = *(const float4*)&Bs[k*64 + tx*4];
            acc[0][0]+=a0*b.x; acc[0][1]+=a0*b.y; acc[0][2]+=a0*b.z; acc[0][3]+=a0*b.w;
            acc[1][0]+=a1*b.x; acc[1][1]+=a1*b.y; acc[1][2]+=a1*b.z; acc[1][3]+=a1*b.w;
            acc[2][0]+=a2*b.x; acc[2][1]+=a2*b.y; acc[2][2]+=a2*b.z; acc[2][3]+=a2*b.w;
            acc[3][0]+=a3*b.x; acc[3][1]+=a3*b.y; acc[3][2]+=a3*b.z; acc[3][3]+=a3*b.w;
        }
        __syncthreads();
    }
    float4 bb;
    bb.x = bias[c0 + tx*4 + 0];
    bb.y = bias[c0 + tx*4 + 1];
    bb.z = bias[c0 + tx*4 + 2];
    bb.w = bias[c0 + tx*4 + 3];
#pragma unroll
    for (int r = 0; r < 4; r++) {
        int l = l0 + ty + 16*r;
        float4 v;
        v.x = acc[r][0] + bb.x; v.y = acc[r][1] + bb.y;
        v.z = acc[r][2] + bb.z; v.w = acc[r][3] + bb.w;
        *(float4*)&g_ye[((size_t)n*LTOT + l)*CHN + c0 + tx*4] = v;
    }
}

/* ---------------- K3: bucket argmax ---------------- */
__global__ void k_bucket()
{
    __shared__ float xr[64];
    __shared__ float rv[128];
    __shared__ int   ri[128];
    const int pix = blockIdx.x;     // n*L + l
    const int t = threadIdx.x;      // 128
    if (t < 64) xr[t] = g_xe[(size_t)pix*CQ + t];
    __syncthreads();
    float acc = 0.f;
#pragma unroll
    for (int k = 0; k < 64; k++) acc += xr[k] * g_mt[k*NCLUS + t];
    rv[t] = acc; ri[t] = t;
    __syncthreads();
    for (int s = 64; s > 0; s >>= 1) {
        if (t < s) {
            if (rv[t + s] > rv[t]) { rv[t] = rv[t + s]; ri[t] = ri[t + s]; }
        }
        __syncthreads();
    }
    if (t == 0) g_bucket[pix] = ri[0];
}

/* ---------------- sort phase 1: local rank + chunk hist ---------------- */
__global__ void k_sort1()
{
    __shared__ int sb[128];
    __shared__ int h[128];
    const int c = blockIdx.x % NCHUNK;
    const int n = blockIdx.x / NCHUNK;
    const int t = threadIdx.x;
    const int l = c*128 + t;
    const int b = g_bucket[n*LTOT + l];
    sb[t] = b; h[t] = 0;
    __syncthreads();
    int r = 0;
    for (int j = 0; j < t; j++) r += (sb[j] == b);
    atomicAdd(&h[b], 1);
    __syncthreads();
    g_lrank[n*LTOT + l] = r;
    g_chist[(n*NCHUNK + c)*NCLUS + t] = h[t];
}

/* ---------------- sort phase 2: scans ---------------- */
__global__ void k_sort2()
{
    __shared__ int sc[128];
    const int n = blockIdx.x;
    const int b = threadIdx.x;
    int run = 0;
    for (int c = 0; c < NCHUNK; c++) {
        int v = g_chist[(n*NCHUNK + c)*NCLUS + b];
        g_cbase[(n*NCHUNK + c)*NCLUS + b] = run;
        run += v;
    }
    sc[b] = run;
    __syncthreads();
    int val = run;
    for (int off = 1; off < 128; off <<= 1) {
        int o = (b >= off) ? sc[b - off] : 0;
        __syncthreads();
        val += o; sc[b] = val;
        __syncthreads();
    }
    int start = val - run;   // exclusive prefix over buckets
    for (int c = 0; c < NCHUNK; c++)
        g_cbase[(n*NCHUNK + c)*NCLUS + b] += start;
}

/* ---------------- sort phase 3: positions ---------------- */
__global__ void k_sort3()
{
    const int c = blockIdx.x % NCHUNK;
    const int n = blockIdx.x / NCHUNK;
    const int t = threadIdx.x;
    const int l = c*128 + t;
    const int b = g_bucket[n*LTOT + l];
    const int pos = g_cbase[(n*NCHUNK + c)*NCLUS + b] + g_lrank[n*LTOT + l];
    g_indices[n*LTOT + pos] = l;
}

/* ---------------- gather + normalize K ---------------- */
__global__ void k_gather()
{
    __shared__ float red[2];
    const int p = blockIdx.x % LTOT;
    const int n = blockIdx.x / LTOT;
    const int t = threadIdx.x;   // 64
    const int idx = g_indices[n*LTOT + p];
    float v = g_xe[((size_t)n*LTOT + idx)*CQ + t];
    g_qs[((size_t)n*LTOT + p)*CQ + t] = v;
    float ss = v*v;
#pragma unroll
    for (int o = 16; o; o >>= 1) ss += __shfl_down_sync(0xFFFFFFFFu, ss, o);
    if ((t & 31) == 0) red[t >> 5] = ss;
    __syncthreads();
    float tot = red[0] + red[1];
    float inv = 1.f / fmaxf(sqrtf(tot), 5e-5f);
    g_kn[((size_t)n*LTOT + p)*CQ + t] = v * inv;
    const float* ysrc = &g_ye[((size_t)n*LTOT + idx)*CHN];
    float* vdst = &g_vs[((size_t)n*LTOT + p)*CHN];
#pragma unroll
    for (int r = 0; r < 4; r++) vdst[t + 64*r] = ysrc[t + 64*r];
}

/* ---------------- QK GEMM (NT), 48x48 tiles ---------------- */
__global__ void k_qk()
{
    __shared__ float Asm[64*49];
    __shared__ float Bsm[64*49];
    const int mt = blockIdx.x % 3;
    const int nt = blockIdx.x / 3;   // 0..8
    const int w  = blockIdx.y;
    const int n  = blockIdx.z;
    const int t  = threadIdx.x;
    const int tx = t & 15, ty = t >> 4;
    const int i0 = mt*48;
    const int j0 = nt*48;
    const int jblk = j0 / WIN;
    const int jj0  = j0 - jblk*WIN;
    const int wsrc = (jblk == 0) ? w : ((jblk == 1) ? ((w + 63) & 63) : ((w + 1) & 63));

    const float* Abase = &g_qs[((size_t)n*LTOT + w*WIN + i0)*CQ];
    const float* Bbase = &g_kn[((size_t)n*LTOT + wsrc*WIN + jj0)*CQ];

    for (int idx = t; idx < 48*64; idx += 256) {
        int row = idx >> 6, k = idx & 63;
        Asm[k*49 + row] = Abase[row*64 + k];
        Bsm[k*49 + row] = Bbase[row*64 + k];
    }
    __syncthreads();

    float acc[3][3];
#pragma unroll
    for (int r = 0; r < 3; r++)
#pragma unroll
        for (int c = 0; c < 3; c++) acc[r][c] = 0.f;

#pragma unroll 4
    for (int k = 0; k < 64; k++) {
        float a0 = Asm[k*49 + ty];
        float a1 = Asm[k*49 + ty + 16];
        float a2 = Asm[k*49 + ty + 32];
        float b0 = Bsm[k*49 + tx*3 + 0];
        float b1 = Bsm[k*49 + tx*3 + 1];
        float b2 = Bsm[k*49 + tx*3 + 2];
        acc[0][0]+=a0*b0; acc[0][1]+=a0*b1; acc[0][2]+=a0*b2;
        acc[1][0]+=a1*b0; acc[1][1]+=a1*b1; acc[1][2]+=a1*b2;
        acc[2][0]+=a2*b0; acc[2][1]+=a2*b1; acc[2][2]+=a2*b2;
    }

    float* C = &g_raw[((size_t)(n*NWIN + w)*WIN + i0)*W3 + j0];
#pragma unroll
    for (int r = 0; r < 3; r++)
#pragma unroll
        for (int c = 0; c < 3; c++)
            C[(size_t)(ty + 16*r)*W3 + tx*3 + c] = acc[r][c];
}

/* ---------------- row softmax (logsumexp), in place ---------------- */
__global__ void k_softmax()
{
    __shared__ float red[128];
    const size_t row = blockIdx.x;
    float* R = &g_raw[row * W3];
    const int t = threadIdx.x;   // 128
    float v0 = R[t];
    float v1 = R[t + 128];
    float v2 = R[t + 256];
    float v3 = (t < 48) ? R[t + 384] : -1e30f;
    float m = fmaxf(fmaxf(v0, v1), fmaxf(v2, v3));
    red[t] = m;
    __syncthreads();
    for (int s = 64; s > 0; s >>= 1) {
        if (t < s) red[t] = fmaxf(red[t], red[t + s]);
        __syncthreads();
    }
    m = red[0];
    __syncthreads();
    float s = expf(v0 - m) + expf(v1 - m) + expf(v2 - m) + ((t < 48) ? expf(v3 - m) : 0.f);
    red[t] = s;
    __syncthreads();
    for (int ss = 64; ss > 0; ss >>= 1) {
        if (t < ss) red[t] += red[t + ss];
        __syncthreads();
    }
    float lse = m + logf(red[0]);
    R[t]       = expf(v0 - lse);
    R[t + 128] = expf(v1 - lse);
    R[t + 256] = expf(v2 - lse);
    if (t < 48) R[t + 384] = expf(v3 - lse);
}

/* ---------------- P@V GEMM (NN) + scatter ---------------- */
__global__ void k_pv()
{
    __shared__ float Asm[16*49];
    __shared__ float Bsm[16*64];
    const int mt = blockIdx.x % 3;
    const int nt = blockIdx.x / 3;  // 0..3
    const int w  = blockIdx.y;
    const int n  = blockIdx.z;
    const int t  = threadIdx.x;
    const int tx = t & 15, ty = t >> 4;
    const int i0 = mt*48, c0 = nt*64;
    const float* A = &g_raw[((size_t)(n*NWIN + w)*WIN + i0)*W3];

    float acc[3][4];
#pragma unroll
    for (int r = 0; r < 3; r++)
#pragma unroll
        for (int c = 0; c < 4; c++) acc[r][c] = 0.f;

    for (int k0 = 0; k0 < W3; k0 += 16) {
        const int jblk = k0 / WIN;
        const int jj0  = k0 - jblk*WIN;
        const int wsrc = (jblk == 0) ? w : ((jblk == 1) ? ((w + 63) & 63) : ((w + 1) & 63));
        const float* B = &g_vs[((size_t)n*LTOT + wsrc*WIN + jj0)*CHN + c0];

        int idx = t;
#pragma unroll
        for (int r = 0; r < 3; r++) {
            int row = idx >> 4, k = idx & 15;
            Asm[k*49 + row] = A[(size_t)row*W3 + k0 + k];
            idx += 256;
        }
        idx = t;
#pragma unroll
        for (int r = 0; r < 4; r++) {
            int kk = idx >> 6, co = idx & 63;
            Bsm[kk*64 + co] = B[(size_t)kk*CHN + co];
            idx += 256;
        }
        __syncthreads();
#pragma unroll
        for (int k = 0; k < 16; k++) {
            float a0 = Asm[k*49 + ty];
            float a1 = Asm[k*49 + ty + 16];
            float a2 = Asm[k*49 + ty + 32];
            float4 b = *(const float4*)&Bsm[k*64 + tx*4];
            acc[0][0]+=a0*b.x; acc[0][1]+=a0*b.y; acc[0][2]+=a0*b.z; acc[0][3]+=a0*b.w;
            acc[1][0]+=a1*b.x; acc[1][1]+=a1*b.y; acc[1][2]+=a1*b.z; acc[1][3]+=a1*b.w;
            acc[2][0]+=a2*b.x; acc[2][1]+=a2*b.y; acc[2][2]+=a2*b.z; acc[2][3]+=a2*b.w;
        }
        __syncthreads();
    }
#pragma unroll
    for (int r = 0; r < 3; r++) {
        int p = w*WIN + i0 + ty + 16*r;
        int l = g_indices[n*LTOT + p];
        float4 v;
        v.x = acc[r][0]; v.y = acc[r][1]; v.z = acc[r][2]; v.w = acc[r][3];
        *(float4*)&g_ret[((size_t)n*LTOT + l)*CHN + c0 + tx*4] = v;
    }
}

/* ---------------- final: out = x + 0.1 * ret^T ---------------- */
__global__ void k_final(const float* __restrict__ x, float* __restrict__ out)
{
    __shared__ float s[32][33];
    const int lt = blockIdx.x;   // 0..287
    const int ct = blockIdx.y;   // 0..7
    const int n  = blockIdx.z;
    const int l0 = lt*32, c0 = ct*32;
    const int tx = threadIdx.x;  // 32
    const int ty = threadIdx.y;  // 8
#pragma unroll
    for (int r = 0; r < 32; r += 8)
        s[ty + r][tx] = g_ret[((size_t)n*LTOT + l0 + ty + r)*CHN + c0 + tx];
    __syncthreads();
#pragma unroll
    for (int r = 0; r < 32; r += 8) {
        int c = c0 + ty + r;
        size_t o = ((size_t)(n*CHN + c))*LTOT + l0 + tx;
        out[o] = x[o] + 0.1f * s[tx][ty + r];
    }
}

/* ---------------- launch ---------------- */
extern "C" void kernel_launch(void* const* d_in, const int* in_sizes, int n_in,
                              void* d_out, int out_size)
{
    const float* input_x = (const float*)d_in[0];
    const float* means   = (const float*)d_in[1];
    const float* w_match = (const float*)d_in[2];
    const float* b_match = (const float*)d_in[3];
    const float* w_asm   = (const float*)d_in[4];
    const float* b_asm   = (const float*)d_in[5];
    float* out = (float*)d_out;

    k_prep<<<(CHN*CHN + CQ*NCLUS + 255)/256, 256>>>(w_asm, means);
    k_conv3<<<dim3(3, HH, NBATCH), 256>>>(input_x, w_match, b_match);
    k_conv1<<<dim3(LTOT/64, CHN/64, NBATCH), 256>>>(input_x, b_asm);
    k_bucket<<<NBATCH*LTOT, 128>>>();
    k_sort1<<<NBATCH*NCHUNK, 128>>>();
    k_sort2<<<NBATCH, 128>>>();
    k_sort3<<<NBATCH*NCHUNK, 128>>>();
    k_gather<<<NBATCH*LTOT, 64>>>();
    k_qk<<<dim3(27, NWIN, NBATCH), 256>>>();
    k_softmax<<<NBATCH*NWIN*WIN, 128>>>();
    k_pv<<<dim3(12, NWIN, NBATCH), 256>>>();
    k_final<<<dim3(LTOT/32, CHN/32, NBATCH), dim3(32, 8)>>>(input_x, out);
}

// round 12
// speedup vs baseline: 1.0016x; 1.0016x over previous
#include <cuda_runtime.h>
#include <math.h>

#define NBATCH 8
#define CHN    256
#define CQ     64
#define NCLUS  128
#define WIN    144
#define HH     96
#define WWID   96
#define LTOT   (HH*WWID)      /* 9216 */
#define NWIN   (LTOT/WIN)     /* 64 */
#define W3     (3*WIN)        /* 432 */
#define NCHUNK (LTOT/128)     /* 72 */

/* ---------------- device scratch ---------------- */
__device__ float g_xe[NBATCH*LTOT*CQ];          // x_embed (n,l,c)
__device__ float g_ye[NBATCH*LTOT*CHN];         // y_embed (n,l,ch)
__device__ float g_wt[CHN*CHN];                 // w_asm transposed [ci][co]
__device__ float g_mt[CQ*NCLUS];                // means transposed [k][c]
__device__ int   g_bucket[NBATCH*LTOT];
__device__ int   g_lrank[NBATCH*LTOT];
__device__ int   g_chist[NBATCH*NCHUNK*NCLUS];
__device__ int   g_cbase[NBATCH*NCHUNK*NCLUS];
__device__ int   g_indices[NBATCH*LTOT];        // sorted pos -> original l
__device__ float g_qs[NBATCH*LTOT*CQ];          // gathered raw x rows (sorted order)
__device__ float g_kn[NBATCH*LTOT*CQ];          // gathered normalized x rows
__device__ float g_vs[NBATCH*LTOT*CHN];         // gathered y rows
__device__ float g_raw[(size_t)NBATCH*NWIN*WIN*W3];  // raw scores / P in place
__device__ float g_ret[NBATCH*LTOT*CHN];        // attention output at ORIGINAL l

/* ---------------- K0: transposes ---------------- */
__global__ void k_prep(const float* __restrict__ wasm, const float* __restrict__ means)
{
    int idx = blockIdx.x * 256 + threadIdx.x;
    if (idx < CHN*CHN) {
        int ci = idx >> 8, co = idx & 255;
        g_wt[idx] = wasm[co*CHN + ci];
    } else {
        int j = idx - CHN*CHN;
        if (j < CQ*NCLUS) {
            int k = j >> 7, c = j & 127;
            g_mt[j] = means[c*CQ + k];   // NR=1 -> means[0][c][k]
        }
    }
}

/* ---------------- K1: conv3x3 -> g_xe ---------------- */
__global__ void k_conv3(const float* __restrict__ x, const float* __restrict__ w,
                        const float* __restrict__ bias)
{
    __shared__ float xin[16*3*34];     // [ci][dy][col]
    __shared__ float ws[16*9*64];      // [ci*9+tap][cout]
    const int wt = blockIdx.x;         // 0..2 (w tile of 32)
    const int h  = blockIdx.y;         // 0..95
    const int n  = blockIdx.z;
    const int t  = threadIdx.x;        // 256
    const int cout = t & 63;
    const int grp  = t >> 6;           // 0..3, 8 pixels each
    const int w0 = wt * 32;

    float acc[8];
    const float bv = bias[cout];
#pragma unroll
    for (int p = 0; p < 8; p++) acc[p] = bv;

    for (int cc = 0; cc < CHN; cc += 16) {
        __syncthreads();
        // weights: 64 cout x 16 ci x 9 taps = 9216 floats
        for (int idx = t; idx < 64*144; idx += 256) {
            int co = idx / 144;
            int r  = idx - co * 144;         // ci*9 + tap
            ws[r*64 + co] = w[co*2304 + cc*9 + r];
        }
        // input: 16 ci x 3 rows x 34 cols
        for (int idx = t; idx < 16*3*34; idx += 256) {
            int ci = idx / 102;
            int r  = idx - ci*102;
            int dy = r / 34;
            int c  = r - dy*34;
            int hi = h + dy - 1;
            int wi = w0 - 1 + c;
            float v = 0.f;
            if (hi >= 0 && hi < HH && wi >= 0 && wi < WWID)
                v = x[((size_t)(n*CHN + cc + ci)*HH + hi)*WWID + wi];
            xin[idx] = v;
        }
        __syncthreads();

        for (int ci = 0; ci < 16; ci++) {
#pragma unroll
            for (int dy = 0; dy < 3; dy++) {
                float xv[10];
                const float* xr = &xin[(ci*3 + dy)*34 + grp*8];
#pragma unroll
                for (int q = 0; q < 10; q++) xv[q] = xr[q];
#pragma unroll
                for (int kx = 0; kx < 3; kx++) {
                    float wv = ws[(ci*9 + dy*3 + kx)*64 + cout];
#pragma unroll
                    for (int p = 0; p < 8; p++) acc[p] += wv * xv[p + kx];
                }
            }
        }
    }
    // store: g_xe[n][l][cout]
#pragma unroll
    for (int p = 0; p < 8; p++) {
        int l = h*WWID + w0 + grp*8 + p;
        g_xe[((size_t)n*LTOT + l)*CQ + cout] = acc[p];
    }
}

/* ---------------- K2: conv1x1 (GEMM) -> g_ye ---------------- */
__global__ void k_conv1(const float* __restrict__ x, const float* __restrict__ bias)
{
    __shared__ float As[16*64];
    __shared__ float Bs[16*64];
    const int lt = blockIdx.x;   // 0..143
    const int ct = blockIdx.y;   // 0..3
    const int n  = blockIdx.z;
    const int t  = threadIdx.x;
    const int tx = t & 15, ty = t >> 4;
    const int l0 = lt*64, c0 = ct*64;
    const float* xn = x + (size_t)n*CHN*LTOT;

    float acc[4][4];
#pragma unroll
    for (int r = 0; r < 4; r++)
#pragma unroll
        for (int c = 0; c < 4; c++) acc[r][c] = 0.f;

    for (int k0 = 0; k0 < CHN; k0 += 16) {
        int idx = t;
#pragma unroll
        for (int r = 0; r < 4; r++) {
            int ci = idx >> 6, ll = idx & 63;
            As[ci*64 + ll] = xn[(size_t)(k0 + ci)*LTOT + l0 + ll];
            idx += 256;
        }
        idx = t;
#pragma unroll
        for (int r = 0; r < 4; r++) {
            int ci = idx >> 6, co = idx & 63;
            Bs[ci*64 + co] = g_wt[(k0 + ci)*CHN + c0 + co];
            idx += 256;
        }
        __syncthreads();
#pragma unroll
        for (int k = 0; k < 16; k++) {
            float a0 = As[k*64 + ty];
            float a1 = As[k*64 + ty + 16];
            float a2 = As[k*64 + ty + 32];
            float a3 = As[k*64 + ty + 48];
            float4 b = *(const float4*)&Bs[k*64 + tx*4];
            acc[0][0]+=a0*b.x; acc[0][1]+=a0*b.y; acc[0][2]+=a0*b.z; acc[0][3]+=a0*b.w;
            acc[1][0]+=a1*b.x; acc[1][1]+=a1*b.y; acc[1][2]+=a1*b.z; acc[1][3]+=a1*b.w;
            acc[2][0]+=a2*b.x; acc[2][1]+=a2*b.y; acc[2][2]+=a2*b.z; acc[2][3]+=a2*b.w;
            acc[3][0]+=a3*b.x; acc[3][1]+=a3*b.y; acc[3][2]+=a3*b.z; acc[3][3]+=a3*b.w;
        }
        __syncthreads();
    }
    float4 bb;
    bb.x = bias[c0 + tx*4 + 0];
    bb.y = bias[c0 + tx*4 + 1];
    bb.z = bias[c0 + tx*4 + 2];
    bb.w = bias[c0 + tx*4 + 3];
#pragma unroll
    for (int r = 0; r < 4; r++) {
        int l = l0 + ty + 16*r;
        float4 v;
        v.x = acc[r][0] + bb.x; v.y = acc[r][1] + bb.y;
        v.z = acc[r][2] + bb.z; v.w = acc[r][3] + bb.w;
        *(float4*)&g_ye[((size_t)n*LTOT + l)*CHN + c0 + tx*4] = v;
    }
}

/* ---------------- K3: bucket argmax ---------------- */
__global__ void k_bucket()
{
    __shared__ float xr[64];
    __shared__ float rv[128];
    __shared__ int   ri[128];
    const int pix = blockIdx.x;     // n*L + l
    const int t = threadIdx.x;      // 128
    if (t < 64) xr[t] = g_xe[(size_t)pix*CQ + t];
    __syncthreads();
    float acc = 0.f;
#pragma unroll
    for (int k = 0; k < 64; k++) acc += xr[k] * g_mt[k*NCLUS + t];
    rv[t] = acc; ri[t] = t;
    __syncthreads();
    for (int s = 64; s > 0; s >>= 1) {
        if (t < s) {
            if (rv[t + s] > rv[t]) { rv[t] = rv[t + s]; ri[t] = ri[t + s]; }
        }
        __syncthreads();
    }
    if (t == 0) g_bucket[pix] = ri[0];
}

/* ---------------- sort phase 1: local rank + chunk hist ---------------- */
__global__ void k_sort1()
{
    __shared__ int sb[128];
    __shared__ int h[128];
    const int c = blockIdx.x % NCHUNK;
    const int n = blockIdx.x / NCHUNK;
    const int t = threadIdx.x;
    const int l = c*128 + t;
    const int b = g_bucket[n*LTOT + l];
    sb[t] = b; h[t] = 0;
    __syncthreads();
    int r = 0;
    for (int j = 0; j < t; j++) r += (sb[j] == b);
    atomicAdd(&h[b], 1);
    __syncthreads();
    g_lrank[n*LTOT + l] = r;
    g_chist[(n*NCHUNK + c)*NCLUS + t] = h[t];
}

/* ---------------- sort phase 2: scans ---------------- */
__global__ void k_sort2()
{
    __shared__ int sc[128];
    const int n = blockIdx.x;
    const int b = threadIdx.x;
    int run = 0;
    for (int c = 0; c < NCHUNK; c++) {
        int v = g_chist[(n*NCHUNK + c)*NCLUS + b];
        g_cbase[(n*NCHUNK + c)*NCLUS + b] = run;
        run += v;
    }
    sc[b] = run;
    __syncthreads();
    int val = run;
    for (int off = 1; off < 128; off <<= 1) {
        int o = (b >= off) ? sc[b - off] : 0;
        __syncthreads();
        val += o; sc[b] = val;
        __syncthreads();
    }
    int start = val - run;   // exclusive prefix over buckets
    for (int c = 0; c < NCHUNK; c++)
        g_cbase[(n*NCHUNK + c)*NCLUS + b] += start;
}

/* ---------------- sort phase 3: positions ---------------- */
__global__ void k_sort3()
{
    const int c = blockIdx.x % NCHUNK;
    const int n = blockIdx.x / NCHUNK;
    const int t = threadIdx.x;
    const int l = c*128 + t;
    const int b = g_bucket[n*LTOT + l];
    const int pos = g_cbase[(n*NCHUNK + c)*NCLUS + b] + g_lrank[n*LTOT + l];
    g_indices[n*LTOT + pos] = l;
}

/* ---------------- gather + normalize K ---------------- */
__global__ void k_gather()
{
    __shared__ float red[2];
    const int p = blockIdx.x % LTOT;
    const int n = blockIdx.x / LTOT;
    const int t = threadIdx.x;   // 64
    const int idx = g_indices[n*LTOT + p];
    float v = g_xe[((size_t)n*LTOT + idx)*CQ + t];
    g_qs[((size_t)n*LTOT + p)*CQ + t] = v;
    float ss = v*v;
#pragma unroll
    for (int o = 16; o; o >>= 1) ss += __shfl_down_sync(0xFFFFFFFFu, ss, o);
    if ((t & 31) == 0) red[t >> 5] = ss;
    __syncthreads();
    float tot = red[0] + red[1];
    float inv = 1.f / fmaxf(sqrtf(tot), 5e-5f);
    g_kn[((size_t)n*LTOT + p)*CQ + t] = v * inv;
    const float* ysrc = &g_ye[((size_t)n*LTOT + idx)*CHN];
    float* vdst = &g_vs[((size_t)n*LTOT + p)*CHN];
#pragma unroll
    for (int r = 0; r < 4; r++) vdst[t + 64*r] = ysrc[t + 64*r];
}

/* ---------------- QK GEMM (NT), 48x48 tiles ---------------- */
__global__ void k_qk()
{
    __shared__ float Asm[64*49];
    __shared__ float Bsm[64*49];
    const int mt = blockIdx.x % 3;
    const int nt = blockIdx.x / 3;   // 0..8
    const int w  = blockIdx.y;
    const int n  = blockIdx.z;
    const int t  = threadIdx.x;
    const int tx = t & 15, ty = t >> 4;
    const int i0 = mt*48;
    const int j0 = nt*48;
    const int jblk = j0 / WIN;
    const int jj0  = j0 - jblk*WIN;
    const int wsrc = (jblk == 0) ? w : ((jblk == 1) ? ((w + 63) & 63) : ((w + 1) & 63));

    const float* Abase = &g_qs[((size_t)n*LTOT + w*WIN + i0)*CQ];
    const float* Bbase = &g_kn[((size_t)n*LTOT + wsrc*WIN + jj0)*CQ];

    for (int idx = t; idx < 48*64; idx += 256) {
        int row = idx >> 6, k = idx & 63;
        Asm[k*49 + row] = Abase[row*64 + k];
        Bsm[k*49 + row] = Bbase[row*64 + k];
    }
    __syncthreads();

    float acc[3][3];
#pragma unroll
    for (int r = 0; r < 3; r++)
#pragma unroll
        for (int c = 0; c < 3; c++) acc[r][c] = 0.f;

#pragma unroll 4
    for (int k = 0; k < 64; k++) {
        float a0 = Asm[k*49 + ty];
        float a1 = Asm[k*49 + ty + 16];
        float a2 = Asm[k*49 + ty + 32];
        float b0 = Bsm[k*49 + tx*3 + 0];
        float b1 = Bsm[k*49 + tx*3 + 1];
        float b2 = Bsm[k*49 + tx*3 + 2];
        acc[0][0]+=a0*b0; acc[0][1]+=a0*b1; acc[0][2]+=a0*b2;
        acc[1][0]+=a1*b0; acc[1][1]+=a1*b1; acc[1][2]+=a1*b2;
        acc[2][0]+=a2*b0; acc[2][1]+=a2*b1; acc[2][2]+=a2*b2;
    }

    float* C = &g_raw[((size_t)(n*NWIN + w)*WIN + i0)*W3 + j0];
#pragma unroll
    for (int r = 0; r < 3; r++)
#pragma unroll
        for (int c = 0; c < 3; c++)
            C[(size_t)(ty + 16*r)*W3 + tx*3 + c] = acc[r][c];
}

/* ---------------- row softmax (logsumexp), in place ---------------- */
__global__ void k_softmax()
{
    __shared__ float red[128];
    const size_t row = blockIdx.x;
    float* R = &g_raw[row * W3];
    const int t = threadIdx.x;   // 128
    float v0 = R[t];
    float v1 = R[t + 128];
    float v2 = R[t + 256];
    float v3 = (t < 48) ? R[t + 384] : -1e30f;
    float m = fmaxf(fmaxf(v0, v1), fmaxf(v2, v3));
    red[t] = m;
    __syncthreads();
    for (int s = 64; s > 0; s >>= 1) {
        if (t < s) red[t] = fmaxf(red[t], red[t + s]);
        __syncthreads();
    }
    m = red[0];
    __syncthreads();
    float s = expf(v0 - m) + expf(v1 - m) + expf(v2 - m) + ((t < 48) ? expf(v3 - m) : 0.f);
    red[t] = s;
    __syncthreads();
    for (int ss = 64; ss > 0; ss >>= 1) {
        if (t < ss) red[t] += red[t + ss];
        __syncthreads();
    }
    float lse = m + logf(red[0]);
    R[t]       = expf(v0 - lse);
    R[t + 128] = expf(v1 - lse);
    R[t + 256] = expf(v2 - lse);
    if (t < 48) R[t + 384] = expf(v3 - lse);
}

/* ---------------- P@V GEMM (NN) + scatter ---------------- */
__global__ void k_pv()
{
    __shared__ float Asm[16*49];
    __shared__ float Bsm[16*64];
    const int mt = blockIdx.x % 3;
    const int nt = blockIdx.x / 3;  // 0..3
    const int w  = blockIdx.y;
    const int n  = blockIdx.z;
    const int t  = threadIdx.x;
    const int tx = t & 15, ty = t >> 4;
    const int i0 = mt*48, c0 = nt*64;
    const float* A = &g_raw[((size_t)(n*NWIN + w)*WIN + i0)*W3];

    float acc[3][4];
#pragma unroll
    for (int r = 0; r < 3; r++)
#pragma unroll
        for (int c = 0; c < 4; c++) acc[r][c] = 0.f;

    for (int k0 = 0; k0 < W3; k0 += 16) {
        const int jblk = k0 / WIN;
        const int jj0  = k0 - jblk*WIN;
        const int wsrc = (jblk == 0) ? w : ((jblk == 1) ? ((w + 63) & 63) : ((w + 1) & 63));
        const float* B = &g_vs[((size_t)n*LTOT + wsrc*WIN + jj0)*CHN + c0];

        int idx = t;
#pragma unroll
        for (int r = 0; r < 3; r++) {
            int row = idx >> 4, k = idx & 15;
            Asm[k*49 + row] = A[(size_t)row*W3 + k0 + k];
            idx += 256;
        }
        idx = t;
#pragma unroll
        for (int r = 0; r < 4; r++) {
            int kk = idx >> 6, co = idx & 63;
            Bsm[kk*64 + co] = B[(size_t)kk*CHN + co];
            idx += 256;
        }
        __syncthreads();
#pragma unroll
        for (int k = 0; k < 16; k++) {
            float a0 = Asm[k*49 + ty];
            float a1 = Asm[k*49 + ty + 16];
            float a2 = Asm[k*49 + ty + 32];
            float4 b = *(const float4*)&Bsm[k*64 + tx*4];
            acc[0][0]+=a0*b.x; acc[0][1]+=a0*b.y; acc[0][2]+=a0*b.z; acc[0][3]+=a0*b.w;
            acc[1][0]+=a1*b.x; acc[1][1]+=a1*b.y; acc[1][2]+=a1*b.z; acc[1][3]+=a1*b.w;
            acc[2][0]+=a2*b.x; acc[2][1]+=a2*b.y; acc[2][2]+=a2*b.z; acc[2][3]+=a2*b.w;
        }
        __syncthreads();
    }
#pragma unroll
    for (int r = 0; r < 3; r++) {
        int p = w*WIN + i0 + ty + 16*r;
        int l = g_indices[n*LTOT + p];
        float4 v;
        v.x = acc[r][0]; v.y = acc[r][1]; v.z = acc[r][2]; v.w = acc[r][3];
        *(float4*)&g_ret[((size_t)n*LTOT + l)*CHN + c0 + tx*4] = v;
    }
}

/* ---------------- final: out = x + 0.1 * ret^T ---------------- */
__global__ void k_final(const float* __restrict__ x, float* __restrict__ out)
{
    __shared__ float s[32][33];
    const int lt = blockIdx.x;   // 0..287
    const int ct = blockIdx.y;   // 0..7
    const int n  = blockIdx.z;
    const int l0 = lt*32, c0 = ct*32;
    const int tx = threadIdx.x;  // 32
    const int ty = threadIdx.y;  // 8
#pragma unroll
    for (int r = 0; r < 32; r += 8)
        s[ty + r][tx] = g_ret[((size_t)n*LTOT + l0 + ty + r)*CHN + c0 + tx];
    __syncthreads();
#pragma unroll
    for (int r = 0; r < 32; r += 8) {
        int c = c0 + ty + r;
        size_t o = ((size_t)(n*CHN + c))*LTOT + l0 + tx;
        out[o] = x[o] + 0.1f * s[tx][ty + r];
    }
}

/* ---------------- launch ---------------- */
extern "C" void kernel_launch(void* const* d_in, const int* in_sizes, int n_in,
                              void* d_out, int out_size)
{
    const float* input_x = (const float*)d_in[0];
    const float* means   = (const float*)d_in[1];
    const float* w_match = (const float*)d_in[2];
    const float* b_match = (const float*)d_in[3];
    const float* w_asm   = (const float*)d_in[4];
    const float* b_asm   = (const float*)d_in[5];
    float* out = (float*)d_out;

    k_prep<<<(CHN*CHN + CQ*NCLUS + 255)/256, 256>>>(w_asm, means);
    k_conv3<<<dim3(3, HH, NBATCH), 256>>>(input_x, w_match, b_match);
    k_conv1<<<dim3(LTOT/64, CHN/64, NBATCH), 256>>>(input_x, b_asm);
    k_bucket<<<NBATCH*LTOT, 128>>>();
    k_sort1<<<NBATCH*NCHUNK, 128>>>();
    k_sort2<<<NBATCH, 128>>>();
    k_sort3<<<NBATCH*NCHUNK, 128>>>();
    k_gather<<<NBATCH*LTOT, 64>>>();
    k_qk<<<dim3(27, NWIN, NBATCH), 256>>>();
    k_softmax<<<NBATCH*NWIN*WIN, 128>>>();
    k_pv<<<dim3(12, NWIN, NBATCH), 256>>>();
    k_final<<<dim3(LTOT/32, CHN/32, NBATCH), dim3(32, 8)>>>(input_x, out);
}

// round 13
// speedup vs baseline: 1.0023x; 1.0007x over previous
#include <cuda_runtime.h>
#include <math.h>

#define NBATCH 8
#define CHN    256
#define CQ     64
#define NCLUS  128
#define WIN    144
#define HH     96
#define WWID   96
#define LTOT   (HH*WWID)      /* 9216 */
#define NWIN   (LTOT/WIN)     /* 64 */
#define W3     (3*WIN)        /* 432 */
#define NCHUNK (LTOT/128)     /* 72 */

/* ---------------- device scratch ---------------- */
__device__ float g_xe[NBATCH*LTOT*CQ];          // x_embed (n,l,c)
__device__ float g_ye[NBATCH*LTOT*CHN];         // y_embed (n,l,ch)
__device__ float g_wt[CHN*CHN];                 // w_asm transposed [ci][co]
__device__ float g_mt[CQ*NCLUS];                // means transposed [k][c]
__device__ int   g_bucket[NBATCH*LTOT];
__device__ int   g_lrank[NBATCH*LTOT];
__device__ int   g_chist[NBATCH*NCHUNK*NCLUS];
__device__ int   g_cbase[NBATCH*NCHUNK*NCLUS];
__device__ int   g_indices[NBATCH*LTOT];        // sorted pos -> original l
__device__ float g_qs[NBATCH*LTOT*CQ];          // gathered raw x rows (sorted order)
__device__ float g_kn[NBATCH*LTOT*CQ];          // gathered normalized x rows
__device__ float g_vs[NBATCH*LTOT*CHN];         // gathered y rows
__device__ float g_raw[(size_t)NBATCH*NWIN*WIN*W3];  // raw scores / P in place
__device__ float g_ret[NBATCH*LTOT*CHN];        // attention output at ORIGINAL l

/* ---------------- K0: transposes ---------------- */
__global__ void k_prep(const float* __restrict__ wasm, const float* __restrict__ means)
{
    int idx = blockIdx.x * 256 + threadIdx.x;
    if (idx < CHN*CHN) {
        int ci = idx >> 8, co = idx & 255;
        g_wt[idx] = wasm[co*CHN + ci];
    } else {
        int j = idx - CHN*CHN;
        if (j < CQ*NCLUS) {
            int k = j >> 7, c = j & 127;
            g_mt[j] = means[c*CQ + k];   // NR=1 -> means[0][c][k]
        }
    }
}

/* ---------------- K1: conv3x3 -> g_xe ---------------- */
__global__ void k_conv3(const float* __restrict__ x, const float* __restrict__ w,
                        const float* __restrict__ bias)
{
    __shared__ float xin[16*3*34];     // [ci][dy][col]
    __shared__ float ws[16*9*64];      // [ci*9+tap][cout]
    const int wt = blockIdx.x;         // 0..2 (w tile of 32)
    const int h  = blockIdx.y;         // 0..95
    const int n  = blockIdx.z;
    const int t  = threadIdx.x;        // 256
    const int cout = t & 63;
    const int grp  = t >> 6;           // 0..3, 8 pixels each
    const int w0 = wt * 32;

    float acc[8];
    const float bv = bias[cout];
#pragma unroll
    for (int p = 0; p < 8; p++) acc[p] = bv;

    for (int cc = 0; cc < CHN; cc += 16) {
        __syncthreads();
        // weights: 64 cout x 16 ci x 9 taps = 9216 floats
        for (int idx = t; idx < 64*144; idx += 256) {
            int co = idx / 144;
            int r  = idx - co * 144;         // ci*9 + tap
            ws[r*64 + co] = w[co*2304 + cc*9 + r];
        }
        // input: 16 ci x 3 rows x 34 cols
        for (int idx = t; idx < 16*3*34; idx += 256) {
            int ci = idx / 102;
            int r  = idx - ci*102;
            int dy = r / 34;
            int c  = r - dy*34;
            int hi = h + dy - 1;
            int wi = w0 - 1 + c;
            float v = 0.f;
            if (hi >= 0 && hi < HH && wi >= 0 && wi < WWID)
                v = x[((size_t)(n*CHN + cc + ci)*HH + hi)*WWID + wi];
            xin[idx] = v;
        }
        __syncthreads();

        for (int ci = 0; ci < 16; ci++) {
#pragma unroll
            for (int dy = 0; dy < 3; dy++) {
                float xv[10];
                const float* xr = &xin[(ci*3 + dy)*34 + grp*8];
#pragma unroll
                for (int q = 0; q < 10; q++) xv[q] = xr[q];
#pragma unroll
                for (int kx = 0; kx < 3; kx++) {
                    float wv = ws[(ci*9 + dy*3 + kx)*64 + cout];
#pragma unroll
                    for (int p = 0; p < 8; p++) acc[p] += wv * xv[p + kx];
                }
            }
        }
    }
    // store: g_xe[n][l][cout]
#pragma unroll
    for (int p = 0; p < 8; p++) {
        int l = h*WWID + w0 + grp*8 + p;
        g_xe[((size_t)n*LTOT + l)*CQ + cout] = acc[p];
    }
}

/* ---------------- K2: conv1x1 (GEMM) -> g_ye ---------------- */
__global__ void k_conv1(const float* __restrict__ x, const float* __restrict__ bias)
{
    __shared__ float As[16*64];
    __shared__ float Bs[16*64];
    const int lt = blockIdx.x;   // 0..143
    const int ct = blockIdx.y;   // 0..3
    const int n  = blockIdx.z;
    const int t  = threadIdx.x;
    const int tx = t & 15, ty = t >> 4;
    const int l0 = lt*64, c0 = ct*64;
    const float* xn = x + (size_t)n*CHN*LTOT;

    float acc[4][4];
#pragma unroll
    for (int r = 0; r < 4; r++)
#pragma unroll
        for (int c = 0; c < 4; c++) acc[r][c] = 0.f;

    for (int k0 = 0; k0 < CHN; k0 += 16) {
        int idx = t;
#pragma unroll
        for (int r = 0; r < 4; r++) {
            int ci = idx >> 6, ll = idx & 63;
            As[ci*64 + ll] = xn[(size_t)(k0 + ci)*LTOT + l0 + ll];
            idx += 256;
        }
        idx = t;
#pragma unroll
        for (int r = 0; r < 4; r++) {
            int ci = idx >> 6, co = idx & 63;
            Bs[ci*64 + co] = g_wt[(k0 + ci)*CHN + c0 + co];
            idx += 256;
        }
        __syncthreads();
#pragma unroll
        for (int k = 0; k < 16; k++) {
            float a0 = As[k*64 + ty];
            float a1 = As[k*64 + ty + 16];
            float a2 = As[k*64 + ty + 32];
            float a3 = As[k*64 + ty + 48];
            float4 b = *(const float4*)&Bs[k*64 + tx*4];
            acc[0][0]+=a0*b.x; acc[0][1]+=a0*b.y; acc[0][2]+=a0*b.z; acc[0][3]+=a0*b.w;
            acc[1][0]+=a1*b.x; acc[1][1]+=a1*b.y; acc[1][2]+=a1*b.z; acc[1][3]+=a1*b.w;
            acc[2][0]+=a2*b.x; acc[2][1]+=a2*b.y; acc[2][2]+=a2*b.z; acc[2][3]+=a2*b.w;
            acc[3][0]+=a3*b.x; acc[3][1]+=a3*b.y; acc[3][2]+=a3*b.z; acc[3][3]+=a3*b.w;
        }
        __syncthreads();
    }
    float4 bb;
    bb.x = bias[c0 + tx*4 + 0];
    bb.y = bias[c0 + tx*4 + 1];
    bb.z = bias[c0 + tx*4 + 2];
    bb.w = bias[c0 + tx*4 + 3];
#pragma unroll
    for (int r = 0; r < 4; r++) {
        int l = l0 + ty + 16*r;
        float4 v;
        v.x = acc[r][0] + bb.x; v.y = acc[r][1] + bb.y;
        v.z = acc[r][2] + bb.z; v.w = acc[r][3] + bb.w;
        *(float4*)&g_ye[((size_t)n*LTOT + l)*CHN + c0 + tx*4] = v;
    }
}

/* ---------------- K3: bucket argmax ---------------- */
__global__ void k_bucket()
{
    __shared__ float xr[64];
    __shared__ float rv[128];
    __shared__ int   ri[128];
    const int pix = blockIdx.x;     // n*L + l
    const int t = threadIdx.x;      // 128
    if (t < 64) xr[t] = g_xe[(size_t)pix*CQ + t];
    __syncthreads();
    float acc = 0.f;
#pragma unroll
    for (int k = 0; k < 64; k++) acc += xr[k] * g_mt[k*NCLUS + t];
    rv[t] = acc; ri[t] = t;
    __syncthreads();
    for (int s = 64; s > 0; s >>= 1) {
        if (t < s) {
            if (rv[t + s] > rv[t]) { rv[t] = rv[t + s]; ri[t] = ri[t + s]; }
        }
        __syncthreads();
    }
    if (t == 0) g_bucket[pix] = ri[0];
}

/* ---------------- sort phase 1: local rank + chunk hist ---------------- */
__global__ void k_sort1()
{
    __shared__ int sb[128];
    __shared__ int h[128];
    const int c = blockIdx.x % NCHUNK;
    const int n = blockIdx.x / NCHUNK;
    const int t = threadIdx.x;
    const int l = c*128 + t;
    const int b = g_bucket[n*LTOT + l];
    sb[t] = b; h[t] = 0;
    __syncthreads();
    int r = 0;
    for (int j = 0; j < t; j++) r += (sb[j] == b);
    atomicAdd(&h[b], 1);
    __syncthreads();
    g_lrank[n*LTOT + l] = r;
    g_chist[(n*NCHUNK + c)*NCLUS + t] = h[t];
}

/* ---------------- sort phase 2: scans ---------------- */
__global__ void k_sort2()
{
    __shared__ int sc[128];
    const int n = blockIdx.x;
    const int b = threadIdx.x;
    int run = 0;
    for (int c = 0; c < NCHUNK; c++) {
        int v = g_chist[(n*NCHUNK + c)*NCLUS + b];
        g_cbase[(n*NCHUNK + c)*NCLUS + b] = run;
        run += v;
    }
    sc[b] = run;
    __syncthreads();
    int val = run;
    for (int off = 1; off < 128; off <<= 1) {
        int o = (b >= off) ? sc[b - off] : 0;
        __syncthreads();
        val += o; sc[b] = val;
        __syncthreads();
    }
    int start = val - run;   // exclusive prefix over buckets
    for (int c = 0; c < NCHUNK; c++)
        g_cbase[(n*NCHUNK + c)*NCLUS + b] += start;
}

/* ---------------- sort phase 3: positions ---------------- */
__global__ void k_sort3()
{
    const int c = blockIdx.x % NCHUNK;
    const int n = blockIdx.x / NCHUNK;
    const int t = threadIdx.x;
    const int l = c*128 + t;
    const int b = g_bucket[n*LTOT + l];
    const int pos = g_cbase[(n*NCHUNK + c)*NCLUS + b] + g_lrank[n*LTOT + l];
    g_indices[n*LTOT + pos] = l;
}

/* ---------------- gather + normalize K ---------------- */
__global__ void k_gather()
{
    __shared__ float red[2];
    const int p = blockIdx.x % LTOT;
    const int n = blockIdx.x / LTOT;
    const int t = threadIdx.x;   // 64
    const int idx = g_indices[n*LTOT + p];
    float v = g_xe[((size_t)n*LTOT + idx)*CQ + t];
    g_qs[((size_t)n*LTOT + p)*CQ + t] = v;
    float ss = v*v;
#pragma unroll
    for (int o = 16; o; o >>= 1) ss += __shfl_down_sync(0xFFFFFFFFu, ss, o);
    if ((t & 31) == 0) red[t >> 5] = ss;
    __syncthreads();
    float tot = red[0] + red[1];
    float inv = 1.f / fmaxf(sqrtf(tot), 5e-5f);
    g_kn[((size_t)n*LTOT + p)*CQ + t] = v * inv;
    const float* ysrc = &g_ye[((size_t)n*LTOT + idx)*CHN];
    float* vdst = &g_vs[((size_t)n*LTOT + p)*CHN];
#pragma unroll
    for (int r = 0; r < 4; r++) vdst[t + 64*r] = ysrc[t + 64*r];
}

/* ---------------- QK GEMM (NT), 48x48 tiles ---------------- */
__global__ void k_qk()
{
    __shared__ float Asm[64*49];
    __shared__ float Bsm[64*49];
    const int mt = blockIdx.x % 3;
    const int nt = blockIdx.x / 3;   // 0..8
    const int w  = blockIdx.y;
    const int n  = blockIdx.z;
    const int t  = threadIdx.x;
    const int tx = t & 15, ty = t >> 4;
    const int i0 = mt*48;
    const int j0 = nt*48;
    const int jblk = j0 / WIN;
    const int jj0  = j0 - jblk*WIN;
    const int wsrc = (jblk == 0) ? w : ((jblk == 1) ? ((w + 63) & 63) : ((w + 1) & 63));

    const float* Abase = &g_qs[((size_t)n*LTOT + w*WIN + i0)*CQ];
    const float* Bbase = &g_kn[((size_t)n*LTOT + wsrc*WIN + jj0)*CQ];

    for (int idx = t; idx < 48*64; idx += 256) {
        int row = idx >> 6, k = idx & 63;
        Asm[k*49 + row] = Abase[row*64 + k];
        Bsm[k*49 + row] = Bbase[row*64 + k];
    }
    __syncthreads();

    float acc[3][3];
#pragma unroll
    for (int r = 0; r < 3; r++)
#pragma unroll
        for (int c = 0; c < 3; c++) acc[r][c] = 0.f;

#pragma unroll 4
    for (int k = 0; k < 64; k++) {
        float a0 = Asm[k*49 + ty];
        float a1 = Asm[k*49 + ty + 16];
        float a2 = Asm[k*49 + ty + 32];
        float b0 = Bsm[k*49 + tx*3 + 0];
        float b1 = Bsm[k*49 + tx*3 + 1];
        float b2 = Bsm[k*49 + tx*3 + 2];
        acc[0][0]+=a0*b0; acc[0][1]+=a0*b1; acc[0][2]+=a0*b2;
        acc[1][0]+=a1*b0; acc[1][1]+=a1*b1; acc[1][2]+=a1*b2;
        acc[2][0]+=a2*b0; acc[2][1]+=a2*b1; acc[2][2]+=a2*b2;
    }

    float* C = &g_raw[((size_t)(n*NWIN + w)*WIN + i0)*W3 + j0];
#pragma unroll
    for (int r = 0; r < 3; r++)
#pragma unroll
        for (int c = 0; c < 3; c++)
            C[(size_t)(ty + 16*r)*W3 + tx*3 + c] = acc[r][c];
}

/* ---------------- row softmax (logsumexp), in place ---------------- */
__global__ void k_softmax()
{
    __shared__ float red[128];
    const size_t row = blockIdx.x;
    float* R = &g_raw[row * W3];
    const int t = threadIdx.x;   // 128
    float v0 = R[t];
    float v1 = R[t + 128];
    float v2 = R[t + 256];
    float v3 = (t < 48) ? R[t + 384] : -1e30f;
    float m = fmaxf(fmaxf(v0, v1), fmaxf(v2, v3));
    red[t] = m;
    __syncthreads();
    for (int s = 64; s > 0; s >>= 1) {
        if (t < s) red[t] = fmaxf(red[t], red[t + s]);
        __syncthreads();
    }
    m = red[0];
    __syncthreads();
    float s = expf(v0 - m) + expf(v1 - m) + expf(v2 - m) + ((t < 48) ? expf(v3 - m) : 0.f);
    red[t] = s;
    __syncthreads();
    for (int ss = 64; ss > 0; ss >>= 1) {
        if (t < ss) red[t] += red[t + ss];
        __syncthreads();
    }
    float lse = m + logf(red[0]);
    R[t]       = expf(v0 - lse);
    R[t + 128] = expf(v1 - lse);
    R[t + 256] = expf(v2 - lse);
    if (t < 48) R[t + 384] = expf(v3 - lse);
}

/* ---------------- P@V GEMM (NN) + scatter ---------------- */
__global__ void k_pv()
{
    __shared__ float Asm[16*49];
    __shared__ float Bsm[16*64];
    const int mt = blockIdx.x % 3;
    const int nt = blockIdx.x / 3;  // 0..3
    const int w  = blockIdx.y;
    const int n  = blockIdx.z;
    const int t  = threadIdx.x;
    const int tx = t & 15, ty = t >> 4;
    const int i0 = mt*48, c0 = nt*64;
    const float* A = &g_raw[((size_t)(n*NWIN + w)*WIN + i0)*W3];

    float acc[3][4];
#pragma unroll
    for (int r = 0; r < 3; r++)
#pragma unroll
        for (int c = 0; c < 4; c++) acc[r][c] = 0.f;

    for (int k0 = 0; k0 < W3; k0 += 16) {
        const int jblk = k0 / WIN;
        const int jj0  = k0 - jblk*WIN;
        const int wsrc = (jblk == 0) ? w : ((jblk == 1) ? ((w + 63) & 63) : ((w + 1) & 63));
        const float* B = &g_vs[((size_t)n*LTOT + wsrc*WIN + jj0)*CHN + c0];

        int idx = t;
#pragma unroll
        for (int r = 0; r < 3; r++) {
            int row = idx >> 4, k = idx & 15;
            Asm[k*49 + row] = A[(size_t)row*W3 + k0 + k];
            idx += 256;
        }
        idx = t;
#pragma unroll
        for (int r = 0; r < 4; r++) {
            int kk = idx >> 6, co = idx & 63;
            Bsm[kk*64 + co] = B[(size_t)kk*CHN + co];
            idx += 256;
        }
        __syncthreads();
#pragma unroll
        for (int k = 0; k < 16; k++) {
            float a0 = Asm[k*49 + ty];
            float a1 = Asm[k*49 + ty + 16];
            float a2 = Asm[k*49 + ty + 32];
            float4 b = *(const float4*)&Bsm[k*64 + tx*4];
            acc[0][0]+=a0*b.x; acc[0][1]+=a0*b.y; acc[0][2]+=a0*b.z; acc[0][3]+=a0*b.w;
            acc[1][0]+=a1*b.x; acc[1][1]+=a1*b.y; acc[1][2]+=a1*b.z; acc[1][3]+=a1*b.w;
            acc[2][0]+=a2*b.x; acc[2][1]+=a2*b.y; acc[2][2]+=a2*b.z; acc[2][3]+=a2*b.w;
        }
        __syncthreads();
    }
#pragma unroll
    for (int r = 0; r < 3; r++) {
        int p = w*WIN + i0 + ty + 16*r;
        int l = g_indices[n*LTOT + p];
        float4 v;
        v.x = acc[r][0]; v.y = acc[r][1]; v.z = acc[r][2]; v.w = acc[r][3];
        *(float4*)&g_ret[((size_t)n*LTOT + l)*CHN + c0 + tx*4] = v;
    }
}

/* ---------------- final: out = x + 0.1 * ret^T ---------------- */
__global__ void k_final(const float* __restrict__ x, float* __restrict__ out)
{
    __shared__ float s[32][33];
    const int lt = blockIdx.x;   // 0..287
    const int ct = blockIdx.y;   // 0..7
    const int n  = blockIdx.z;
    const int l0 = lt*32, c0 = ct*32;
    const int tx = threadIdx.x;  // 32
    const int ty = threadIdx.y;  // 8
#pragma unroll
    for (int r = 0; r < 32; r += 8)
        s[ty + r][tx] = g_ret[((size_t)n*LTOT + l0 + ty + r)*CHN + c0 + tx];
    __syncthreads();
#pragma unroll
    for (int r = 0; r < 32; r += 8) {
        int c = c0 + ty + r;
        size_t o = ((size_t)(n*CHN + c))*LTOT + l0 + tx;
        out[o] = x[o] + 0.1f * s[tx][ty + r];
    }
}

/* ---------------- launch ---------------- */
extern "C" void kernel_launch(void* const* d_in, const int* in_sizes, int n_in,
                              void* d_out, int out_size)
{
    const float* input_x = (const float*)d_in[0];
    const float* means   = (const float*)d_in[1];
    const float* w_match = (const float*)d_in[2];
    const float* b_match = (const float*)d_in[3];
    const float* w_asm   = (const float*)d_in[4];
    const float* b_asm   = (const float*)d_in[5];
    float* out = (float*)d_out;

    k_prep<<<(CHN*CHN + CQ*NCLUS + 255)/256, 256>>>(w_asm, means);
    k_conv3<<<dim3(3, HH, NBATCH), 256>>>(input_x, w_match, b_match);
    k_conv1<<<dim3(LTOT/64, CHN/64, NBATCH), 256>>>(input_x, b_asm);
    k_bucket<<<NBATCH*LTOT, 128>>>();
    k_sort1<<<NBATCH*NCHUNK, 128>>>();
    k_sort2<<<NBATCH, 128>>>();
    k_sort3<<<NBATCH*NCHUNK, 128>>>();
    k_gather<<<NBATCH*LTOT, 64>>>();
    k_qk<<<dim3(27, NWIN, NBATCH), 256>>>();
    k_softmax<<<NBATCH*NWIN*WIN, 128>>>();
    k_pv<<<dim3(12, NWIN, NBATCH), 256>>>();
    k_final<<<dim3(LTOT/32, CHN/32, NBATCH), dim3(32, 8)>>>(input_x, out);
}